// round 5
// baseline (speedup 1.0000x reference)
#include <cuda_runtime.h>

// Bilinear resample, 1 pixel per thread, 2D-tiled blocks (32x8) for L1 reuse
// of gathered image rows. Branchless clamp+mask gathers (bit-identical to
// per-corner zero padding).
// imgs: (B,1024,1024,1) f32, dvfs: (B,1024,1024,2) f32, out: (B,1024,1024,1) f32.

#define HH 1024
#define WW 1024
#define HW (HH * WW)

__global__ void __launch_bounds__(256)
bilinear_kernel(const float* __restrict__ imgs,
                const float* __restrict__ dvfs,
                float* __restrict__ out) {
    int w = blockIdx.x * 32 + threadIdx.x;
    int h = blockIdx.y * 8  + threadIdx.y;
    int b = blockIdx.z;

    const float* img = imgs + b * HW;
    int idx = (h << 10) | w;               // within-image pixel index
    size_t gidx = (size_t)b * HW + idx;

    // dvfs interleaved (x,y); streaming (touch-once)
    float2 d = __ldcs(reinterpret_cast<const float2*>(dvfs + gidx * 2));

    float fx = (float)w + d.x;
    float fy = (float)h + d.y;
    float x0f = floorf(fx);
    float y0f = floorf(fy);
    float wx = fx - x0f;
    float wy = fy - y0f;
    int x0 = (int)x0f;
    int y0 = (int)y0f;
    int x1 = x0 + 1;
    int y1 = y0 + 1;

    float vx0 = (x0 >= 0 && x0 < WW) ? 1.0f : 0.0f;
    float vx1 = (x1 >= 0 && x1 < WW) ? 1.0f : 0.0f;
    float vy0 = (y0 >= 0 && y0 < HH) ? 1.0f : 0.0f;
    float vy1 = (y1 >= 0 && y1 < HH) ? 1.0f : 0.0f;

    int x0c = min(max(x0, 0), WW - 1);
    int x1c = min(max(x1, 0), WW - 1);
    int y0c = min(max(y0, 0), HH - 1);
    int y1c = min(max(y1, 0), HH - 1);

    const float* r0 = img + (y0c << 10);
    const float* r1 = img + (y1c << 10);

    // 4 independent gathers; addresses within a warp span ~128B -> few L1 wavefronts
    float v00 = __ldg(r0 + x0c);
    float v01 = __ldg(r0 + x1c);
    float v10 = __ldg(r1 + x0c);
    float v11 = __ldg(r1 + x1c);

    v00 *= vy0 * vx0;
    v01 *= vy0 * vx1;
    v10 *= vy1 * vx0;
    v11 *= vy1 * vx1;

    float omx = 1.0f - wx;
    float omy = 1.0f - wy;
    float top = v00 * omx + v01 * wx;
    float bot = v10 * omx + v11 * wx;
    float res = top * omy + bot * wy;

    __stcs(out + gidx, res);
}

extern "C" void kernel_launch(void* const* d_in, const int* in_sizes, int n_in,
                              void* d_out, int out_size) {
    const float* imgs = (const float*)d_in[0];
    const float* dvfs = (const float*)d_in[1];
    float* out = (float*)d_out;

    dim3 block(32, 8, 1);
    dim3 grid(WW / 32, HH / 8, out_size / HW);   // (32, 128, B)
    bilinear_kernel<<<grid, block>>>(imgs, dvfs, out);
}

// round 9
// speedup vs baseline: 1.7964x; 1.7964x over previous
#include <cuda_runtime.h>

// Bilinear resample: out[b,h,w] = bilinear(imgs[b], (w+dx, h+dy)) with
// zero-padding for out-of-bounds corners.
// imgs: (B,1024,1024,1) f32, dvfs: (B,1024,1024,2) f32, out: (B,1024,1024,1) f32.
//
// R1 structure (2 px/thread, 1D linear, predicated @P gathers, float4/float2 I/O)
// + streaming cache hints on the touch-once dvfs/out streams so L1 keeps the
// reuse-bearing img gather lines.

#define HH 1024
#define WW 1024
#define HW (HH * WW)

__device__ __forceinline__ float bilin_one(const float* __restrict__ img,
                                           int h, int w, float dx, float dy) {
    float fx = (float)w + dx;
    float fy = (float)h + dy;
    float x0f = floorf(fx);
    float y0f = floorf(fy);
    float wx = fx - x0f;
    float wy = fy - y0f;
    int x0 = (int)x0f;
    int y0 = (int)y0f;
    int x1 = x0 + 1;
    int y1 = y0 + 1;

    bool vx0 = (x0 >= 0) & (x0 < WW);
    bool vx1 = (x1 >= 0) & (x1 < WW);
    bool vy0 = (y0 >= 0) & (y0 < HH);
    bool vy1 = (y1 >= 0) & (y1 < HH);

    float v00 = 0.f, v01 = 0.f, v10 = 0.f, v11 = 0.f;
    if (vy0) {
        const float* row = img + (y0 << 10);
        if (vx0) v00 = __ldg(row + x0);
        if (vx1) v01 = __ldg(row + x1);
    }
    if (vy1) {
        const float* row = img + (y1 << 10);
        if (vx0) v10 = __ldg(row + x0);
        if (vx1) v11 = __ldg(row + x1);
    }

    float omx = 1.0f - wx;
    float omy = 1.0f - wy;
    float top = v00 * omx + v01 * wx;
    float bot = v10 * omx + v11 * wx;
    return top * omy + bot * wy;
}

__global__ void __launch_bounds__(256)
bilinear_kernel(const float* __restrict__ imgs,
                const float* __restrict__ dvfs,
                float* __restrict__ out,
                int n_pairs) {
    int t = blockIdx.x * blockDim.x + threadIdx.x;
    if (t >= n_pairs) return;

    int idx = t * 2;                       // first pixel of the pair
    int w = idx & (WW - 1);                // even, so w and w+1 share a row
    int h = (idx >> 10) & (HH - 1);
    int b = idx >> 20;

    const float* img = imgs + b * HW;

    // dvfs packed (x,y) interleaved: pixels idx, idx+1 -> 4 floats, 16B aligned.
    // Streaming (touch-once): evict-first, keep L1 for img gather lines.
    float4 d = __ldcs(reinterpret_cast<const float4*>(dvfs + (size_t)idx * 2));

    float r0 = bilin_one(img, h, w,     d.x, d.y);
    float r1 = bilin_one(img, h, w + 1, d.z, d.w);

    __stcs(reinterpret_cast<float2*>(out + idx), make_float2(r0, r1));
}

extern "C" void kernel_launch(void* const* d_in, const int* in_sizes, int n_in,
                              void* d_out, int out_size) {
    const float* imgs = (const float*)d_in[0];
    const float* dvfs = (const float*)d_in[1];
    float* out = (float*)d_out;

    int total = out_size;          // B*H*W
    int n_pairs = total / 2;
    int threads = 256;
    int blocks = (n_pairs + threads - 1) / threads;
    bilinear_kernel<<<blocks, threads>>>(imgs, dvfs, out, n_pairs);
}